// round 1
// baseline (speedup 1.0000x reference)
#include <cuda_runtime.h>

#define NEG_INF -1000000000.0f

static constexpr int B = 8, T = 2048, S = 2048, H = 64;
static constexpr int TM = 128;   // t-rows per block
static constexpr int TN = 128;   // s-cols per tile
static constexpr int NTHR = 256;

// Shared layout (float units):
// [0,128)   m      (row running max)
// [128,256) l      (row running sum-exp)
// [256,384) invl
// area @384:
//   pass1: Qs[128*64] | Kst[64*128] | msk[128] (int)
//   pass2: Ps[128*128] | Vs[128*64]
static constexpr int QS_OFF  = 384;
static constexpr int KST_OFF = QS_OFF + TM * H;        // 384 + 8192
static constexpr int MSK_OFF = KST_OFF + H * TN;       // + 8192
static constexpr int PS_OFF  = 384;
static constexpr int VS_OFF  = PS_OFF + TM * TN;       // 384 + 16384
static constexpr int SMEM_FLOATS = VS_OFF + TN * H;    // 24960
static constexpr int SMEM_BYTES  = SMEM_FLOATS * 4;    // 99840 B

// Swizzled shared indices (XOR keeps float4 alignment: swz is a multiple of 4)
__device__ __forceinline__ int swzQ(int r, int kk) { return r * 64  + (kk ^ (((r  >> 3) & 7) << 2)); }
__device__ __forceinline__ int swzK(int kk, int c) { return kk * 128 + (c  ^ (((kk >> 2) & 7) << 2)); }
__device__ __forceinline__ int swzP(int r, int c)  { return r * 128 + (c  ^ (((r  >> 3) & 7) << 2)); }

extern __shared__ float smf[];

__global__ void __launch_bounds__(NTHR, 1)
attn_kernel(const float* __restrict__ q, const float* __restrict__ k,
            const float* __restrict__ v, const int* __restrict__ mask,
            float* __restrict__ out)
{
    const int bx  = blockIdx.x;
    const int b   = bx >> 4;            // T/TM = 16 row-tiles per batch
    const int t0  = (bx & 15) << 7;
    const int tid = threadIdx.x;

    const float* qb = q + ((size_t)b * T + t0) * H;
    const float* kb = k + (size_t)b * S * H;
    const float* vb = v + (size_t)b * S * H;
    const int*   mb = mask + (size_t)b * S;
    float* pout = out + (size_t)B * T * H + ((size_t)b * T + t0) * S;
    float* oout = out + ((size_t)b * T + t0) * H;

    if (tid < 128) { smf[tid] = -3.0e38f; smf[128 + tid] = 0.0f; }

    // ---------------- Pass 1: scores + online softmax stats ----------------
    // Load Q tile once (swizzled, linear-ish copy)
    for (int i4 = tid * 4; i4 < TM * H; i4 += NTHR * 4) {
        int r = i4 >> 6, kk = i4 & 63;
        float4 val = *(const float4*)(qb + i4);
        *(float4*)&smf[QS_OFF + swzQ(r, kk)] = val;
    }
    __syncthreads();

    const int ty1 = tid >> 4;      // 0..15 -> 8 rows each
    const int tx1 = tid & 15;      // 0..15 -> 8 cols each
    const int r1  = ty1 * 8;
    const int c1  = tx1 * 8;
    int* msks = (int*)(smf + MSK_OFF);

    for (int s0 = 0; s0 < S; s0 += TN) {
        // K tile, transposed into Kst[kk][c] with XOR swizzle
        for (int i4 = tid * 4; i4 < TN * H; i4 += NTHR * 4) {
            int c = i4 >> 6, kk = i4 & 63;
            float4 val = *(const float4*)(kb + (size_t)s0 * H + i4);
            smf[KST_OFF + swzK(kk + 0, c)] = val.x;
            smf[KST_OFF + swzK(kk + 1, c)] = val.y;
            smf[KST_OFF + swzK(kk + 2, c)] = val.z;
            smf[KST_OFF + swzK(kk + 3, c)] = val.w;
        }
        if (tid < TN) msks[tid] = mb[s0 + tid];
        __syncthreads();

        float acc[8][8];
        #pragma unroll
        for (int i = 0; i < 8; i++)
            #pragma unroll
            for (int j = 0; j < 8; j++) acc[i][j] = 0.0f;

        #pragma unroll 1
        for (int kk = 0; kk < H; kk += 4) {
            float4 a4[8];
            #pragma unroll
            for (int i = 0; i < 8; i++)
                a4[i] = *(const float4*)&smf[QS_OFF + swzQ(r1 + i, kk)];
            #pragma unroll
            for (int u = 0; u < 4; u++) {
                const float4 b0 = *(const float4*)&smf[KST_OFF + swzK(kk + u, c1)];
                const float4 b1 = *(const float4*)&smf[KST_OFF + swzK(kk + u, c1 + 4)];
                #pragma unroll
                for (int i = 0; i < 8; i++) {
                    float av = (u == 0) ? a4[i].x : (u == 1) ? a4[i].y : (u == 2) ? a4[i].z : a4[i].w;
                    acc[i][0] += av * b0.x;  acc[i][1] += av * b0.y;
                    acc[i][2] += av * b0.z;  acc[i][3] += av * b0.w;
                    acc[i][4] += av * b1.x;  acc[i][5] += av * b1.y;
                    acc[i][6] += av * b1.z;  acc[i][7] += av * b1.w;
                }
            }
        }

        // mask, store raw scores, update online (m, l) per row
        int mr[8];
        #pragma unroll
        for (int j = 0; j < 8; j++) mr[j] = msks[c1 + j];

        #pragma unroll
        for (int i = 0; i < 8; i++) {
            const int row = r1 + i;
            float rmax = -3.0e38f;
            #pragma unroll
            for (int j = 0; j < 8; j++) {
                float sc = mr[j] ? acc[i][j] : NEG_INF;
                acc[i][j] = sc;
                rmax = fmaxf(rmax, sc);
            }
            float* prow = pout + (size_t)row * S + s0 + c1;
            *(float4*)prow       = make_float4(acc[i][0], acc[i][1], acc[i][2], acc[i][3]);
            *(float4*)(prow + 4) = make_float4(acc[i][4], acc[i][5], acc[i][6], acc[i][7]);

            #pragma unroll
            for (int off = 8; off; off >>= 1)
                rmax = fmaxf(rmax, __shfl_xor_sync(0xffffffffu, rmax, off));
            float oldm = smf[row];                  // read before any lane writes
            float newm = fmaxf(oldm, rmax);
            float ls = 0.0f;
            #pragma unroll
            for (int j = 0; j < 8; j++) ls += __expf(acc[i][j] - newm);
            #pragma unroll
            for (int off = 8; off; off >>= 1)       // shfl = warp barrier: reads done
                ls += __shfl_xor_sync(0xffffffffu, ls, off);
            if (tx1 == 0) {
                smf[128 + row] = smf[128 + row] * __expf(oldm - newm) + ls;
                smf[row] = newm;
            }
        }
        __syncthreads();
    }

    // invl
    if (tid < 128) smf[256 + tid] = 1.0f / smf[128 + tid];
    __syncthreads();

    // ---------------- Pass 2: normalize p (write final), O = P @ V ----------------
    const int half = tid >> 7;      // split-k halves of each 128-col tile
    const int hid  = tid & 127;
    const int ty2  = hid >> 3;      // 0..15 -> 8 rows each
    const int tx2  = hid & 7;       // 0..7  -> 8 h each
    const int r2   = ty2 * 8;
    const int h2   = tx2 * 8;
    const int cb   = half * 64;

    float oa[8][8];
    #pragma unroll
    for (int i = 0; i < 8; i++)
        #pragma unroll
        for (int j = 0; j < 8; j++) oa[i][j] = 0.0f;

    for (int s0 = 0; s0 < S; s0 += TN) {
        // reload raw scores (L2-hot), finalize p, write back + stage in smem
        for (int i4 = tid * 4; i4 < TM * TN; i4 += NTHR * 4) {
            int r = i4 >> 7, c = i4 & 127;
            float* g = pout + (size_t)r * S + s0 + c;
            float4 val = *(float4*)g;
            float mrow = smf[r], il = smf[256 + r];
            val.x = __expf(val.x - mrow) * il;
            val.y = __expf(val.y - mrow) * il;
            val.z = __expf(val.z - mrow) * il;
            val.w = __expf(val.w - mrow) * il;
            *(float4*)g = val;
            *(float4*)&smf[PS_OFF + swzP(r, c)] = val;
        }
        for (int i4 = tid * 4; i4 < TN * H; i4 += NTHR * 4)
            *(float4*)&smf[VS_OFF + i4] = *(const float4*)(vb + (size_t)s0 * H + i4);
        __syncthreads();

        #pragma unroll 4
        for (int c = 0; c < 64; c++) {
            const int cc = cb + c;
            const float4 v0 = *(const float4*)&smf[VS_OFF + cc * 64 + h2];
            const float4 v1 = *(const float4*)&smf[VS_OFF + cc * 64 + h2 + 4];
            #pragma unroll
            for (int i = 0; i < 8; i++) {
                const float pv = smf[PS_OFF + swzP(r2 + i, cc)];
                oa[i][0] += pv * v0.x;  oa[i][1] += pv * v0.y;
                oa[i][2] += pv * v0.z;  oa[i][3] += pv * v0.w;
                oa[i][4] += pv * v1.x;  oa[i][5] += pv * v1.y;
                oa[i][6] += pv * v1.z;  oa[i][7] += pv * v1.w;
            }
        }
        __syncthreads();
    }

    // combine the two split-k halves via smem, write O
    float* Ob = smf + PS_OFF;   // reuse, free after last sync
    if (half == 0) {
        #pragma unroll
        for (int i = 0; i < 8; i++) {
            *(float4*)&Ob[(r2 + i) * 64 + h2]     = make_float4(oa[i][0], oa[i][1], oa[i][2], oa[i][3]);
            *(float4*)&Ob[(r2 + i) * 64 + h2 + 4] = make_float4(oa[i][4], oa[i][5], oa[i][6], oa[i][7]);
        }
    }
    __syncthreads();
    if (half == 1) {
        #pragma unroll
        for (int i = 0; i < 8; i++) {
            float* og = oout + (size_t)(r2 + i) * H + h2;
            float4 p0 = *(const float4*)&Ob[(r2 + i) * 64 + h2];
            float4 p1 = *(const float4*)&Ob[(r2 + i) * 64 + h2 + 4];
            *(float4*)og       = make_float4(p0.x + oa[i][0], p0.y + oa[i][1], p0.z + oa[i][2], p0.w + oa[i][3]);
            *(float4*)(og + 4) = make_float4(p1.x + oa[i][4], p1.y + oa[i][5], p1.z + oa[i][6], p1.w + oa[i][7]);
        }
    }
}

extern "C" void kernel_launch(void* const* d_in, const int* in_sizes, int n_in,
                              void* d_out, int out_size)
{
    const float* q    = (const float*)d_in[0];
    const float* keys = (const float*)d_in[1];
    const float* vals = (const float*)d_in[2];
    const int*   mask = (const int*)d_in[3];
    float* out = (float*)d_out;

    cudaFuncSetAttribute(attn_kernel, cudaFuncAttributeMaxDynamicSharedMemorySize, SMEM_BYTES);
    attn_kernel<<<B * (T / TM), NTHR, SMEM_BYTES>>>(q, keys, vals, mask, out);
}

// round 2
// speedup vs baseline: 1.0034x; 1.0034x over previous
#include <cuda_runtime.h>

#define NEG_INF -1000000000.0f

static constexpr int B = 8, T = 2048, S = 2048, H = 64;
static constexpr int TM = 128;   // t-rows per block
static constexpr int TN = 128;   // s-cols per tile
static constexpr int NTHR = 256;

// Shared layout (float units):
// [0,128)   m      (row running max)
// [128,256) l      (row running sum-exp)
// [256,384) invl
// area @384:
//   pass1: Qs[128*64] | Kst[64*128] | msk[128] (int)
//   pass2: Ps[128*128] | Vs[128*64]
static constexpr int QS_OFF  = 384;
static constexpr int KST_OFF = QS_OFF + TM * H;        // 384 + 8192
static constexpr int MSK_OFF = KST_OFF + H * TN;       // + 8192
static constexpr int PS_OFF  = 384;
static constexpr int VS_OFF  = PS_OFF + TM * TN;       // 384 + 16384
static constexpr int SMEM_FLOATS = VS_OFF + TN * H;    // 24960
static constexpr int SMEM_BYTES  = SMEM_FLOATS * 4;    // 99840 B

// Swizzled shared indices (XOR keeps float4 alignment: swz is a multiple of 4)
__device__ __forceinline__ int swzQ(int r, int kk) { return r * 64  + (kk ^ (((r  >> 3) & 7) << 2)); }
__device__ __forceinline__ int swzK(int kk, int c) { return kk * 128 + (c  ^ (((kk >> 2) & 7) << 2)); }
__device__ __forceinline__ int swzP(int r, int c)  { return r * 128 + (c  ^ (((r  >> 3) & 7) << 2)); }

extern __shared__ float smf[];

__global__ void __launch_bounds__(NTHR, 1)
attn_kernel(const float* __restrict__ q, const float* __restrict__ k,
            const float* __restrict__ v, const int* __restrict__ mask,
            float* __restrict__ out)
{
    const int bx  = blockIdx.x;
    const int b   = bx >> 4;            // T/TM = 16 row-tiles per batch
    const int t0  = (bx & 15) << 7;
    const int tid = threadIdx.x;

    const float* qb = q + ((size_t)b * T + t0) * H;
    const float* kb = k + (size_t)b * S * H;
    const float* vb = v + (size_t)b * S * H;
    const int*   mb = mask + (size_t)b * S;
    float* pout = out + (size_t)B * T * H + ((size_t)b * T + t0) * S;
    float* oout = out + ((size_t)b * T + t0) * H;

    if (tid < 128) { smf[tid] = -3.0e38f; smf[128 + tid] = 0.0f; }

    // ---------------- Pass 1: scores + online softmax stats ----------------
    // Load Q tile once (swizzled, linear-ish copy)
    for (int i4 = tid * 4; i4 < TM * H; i4 += NTHR * 4) {
        int r = i4 >> 6, kk = i4 & 63;
        float4 val = *(const float4*)(qb + i4);
        *(float4*)&smf[QS_OFF + swzQ(r, kk)] = val;
    }
    __syncthreads();

    const int ty1 = tid >> 4;      // 0..15 -> 8 rows each
    const int tx1 = tid & 15;      // 0..15 -> 8 cols each
    const int r1  = ty1 * 8;
    const int c1  = tx1 * 8;
    int* msks = (int*)(smf + MSK_OFF);

    for (int s0 = 0; s0 < S; s0 += TN) {
        // K tile, transposed into Kst[kk][c] with XOR swizzle
        for (int i4 = tid * 4; i4 < TN * H; i4 += NTHR * 4) {
            int c = i4 >> 6, kk = i4 & 63;
            float4 val = *(const float4*)(kb + (size_t)s0 * H + i4);
            smf[KST_OFF + swzK(kk + 0, c)] = val.x;
            smf[KST_OFF + swzK(kk + 1, c)] = val.y;
            smf[KST_OFF + swzK(kk + 2, c)] = val.z;
            smf[KST_OFF + swzK(kk + 3, c)] = val.w;
        }
        if (tid < TN) msks[tid] = mb[s0 + tid];
        __syncthreads();

        float acc[8][8];
        #pragma unroll
        for (int i = 0; i < 8; i++)
            #pragma unroll
            for (int j = 0; j < 8; j++) acc[i][j] = 0.0f;

        #pragma unroll 1
        for (int kk = 0; kk < H; kk += 4) {
            float4 a4[8];
            #pragma unroll
            for (int i = 0; i < 8; i++)
                a4[i] = *(const float4*)&smf[QS_OFF + swzQ(r1 + i, kk)];
            #pragma unroll
            for (int u = 0; u < 4; u++) {
                const float4 b0 = *(const float4*)&smf[KST_OFF + swzK(kk + u, c1)];
                const float4 b1 = *(const float4*)&smf[KST_OFF + swzK(kk + u, c1 + 4)];
                #pragma unroll
                for (int i = 0; i < 8; i++) {
                    float av = (u == 0) ? a4[i].x : (u == 1) ? a4[i].y : (u == 2) ? a4[i].z : a4[i].w;
                    acc[i][0] += av * b0.x;  acc[i][1] += av * b0.y;
                    acc[i][2] += av * b0.z;  acc[i][3] += av * b0.w;
                    acc[i][4] += av * b1.x;  acc[i][5] += av * b1.y;
                    acc[i][6] += av * b1.z;  acc[i][7] += av * b1.w;
                }
            }
        }

        // mask, store raw scores, update online (m, l) per row
        int mr[8];
        #pragma unroll
        for (int j = 0; j < 8; j++) mr[j] = msks[c1 + j];

        #pragma unroll
        for (int i = 0; i < 8; i++) {
            const int row = r1 + i;
            float rmax = -3.0e38f;
            #pragma unroll
            for (int j = 0; j < 8; j++) {
                float sc = mr[j] ? acc[i][j] : NEG_INF;
                acc[i][j] = sc;
                rmax = fmaxf(rmax, sc);
            }
            float* prow = pout + (size_t)row * S + s0 + c1;
            *(float4*)prow       = make_float4(acc[i][0], acc[i][1], acc[i][2], acc[i][3]);
            *(float4*)(prow + 4) = make_float4(acc[i][4], acc[i][5], acc[i][6], acc[i][7]);

            #pragma unroll
            for (int off = 8; off; off >>= 1)
                rmax = fmaxf(rmax, __shfl_xor_sync(0xffffffffu, rmax, off));
            float oldm = smf[row];                  // read before any lane writes
            float newm = fmaxf(oldm, rmax);
            float ls = 0.0f;
            #pragma unroll
            for (int j = 0; j < 8; j++) ls += __expf(acc[i][j] - newm);
            #pragma unroll
            for (int off = 8; off; off >>= 1)       // shfl = warp barrier: reads done
                ls += __shfl_xor_sync(0xffffffffu, ls, off);
            if (tx1 == 0) {
                smf[128 + row] = smf[128 + row] * __expf(oldm - newm) + ls;
                smf[row] = newm;
            }
        }
        __syncthreads();
    }

    // invl
    if (tid < 128) smf[256 + tid] = 1.0f / smf[128 + tid];
    __syncthreads();

    // ---------------- Pass 2: normalize p (write final), O = P @ V ----------------
    const int half = tid >> 7;      // split-k halves of each 128-col tile
    const int hid  = tid & 127;
    const int ty2  = hid >> 3;      // 0..15 -> 8 rows each
    const int tx2  = hid & 7;       // 0..7  -> 8 h each
    const int r2   = ty2 * 8;
    const int h2   = tx2 * 8;
    const int cb   = half * 64;

    float oa[8][8];
    #pragma unroll
    for (int i = 0; i < 8; i++)
        #pragma unroll
        for (int j = 0; j < 8; j++) oa[i][j] = 0.0f;

    for (int s0 = 0; s0 < S; s0 += TN) {
        // reload raw scores (L2-hot), finalize p, write back + stage in smem
        for (int i4 = tid * 4; i4 < TM * TN; i4 += NTHR * 4) {
            int r = i4 >> 7, c = i4 & 127;
            float* g = pout + (size_t)r * S + s0 + c;
            float4 val = *(float4*)g;
            float mrow = smf[r], il = smf[256 + r];
            val.x = __expf(val.x - mrow) * il;
            val.y = __expf(val.y - mrow) * il;
            val.z = __expf(val.z - mrow) * il;
            val.w = __expf(val.w - mrow) * il;
            *(float4*)g = val;
            *(float4*)&smf[PS_OFF + swzP(r, c)] = val;
        }
        for (int i4 = tid * 4; i4 < TN * H; i4 += NTHR * 4)
            *(float4*)&smf[VS_OFF + i4] = *(const float4*)(vb + (size_t)s0 * H + i4);
        __syncthreads();

        #pragma unroll 4
        for (int c = 0; c < 64; c++) {
            const int cc = cb + c;
            const float4 v0 = *(const float4*)&smf[VS_OFF + cc * 64 + h2];
            const float4 v1 = *(const float4*)&smf[VS_OFF + cc * 64 + h2 + 4];
            #pragma unroll
            for (int i = 0; i < 8; i++) {
                const float pv = smf[PS_OFF + swzP(r2 + i, cc)];
                oa[i][0] += pv * v0.x;  oa[i][1] += pv * v0.y;
                oa[i][2] += pv * v0.z;  oa[i][3] += pv * v0.w;
                oa[i][4] += pv * v1.x;  oa[i][5] += pv * v1.y;
                oa[i][6] += pv * v1.z;  oa[i][7] += pv * v1.w;
            }
        }
        __syncthreads();
    }

    // combine the two split-k halves via smem, write O
    float* Ob = smf + PS_OFF;   // reuse, free after last sync
    if (half == 0) {
        #pragma unroll
        for (int i = 0; i < 8; i++) {
            *(float4*)&Ob[(r2 + i) * 64 + h2]     = make_float4(oa[i][0], oa[i][1], oa[i][2], oa[i][3]);
            *(float4*)&Ob[(r2 + i) * 64 + h2 + 4] = make_float4(oa[i][4], oa[i][5], oa[i][6], oa[i][7]);
        }
    }
    __syncthreads();
    if (half == 1) {
        #pragma unroll
        for (int i = 0; i < 8; i++) {
            float* og = oout + (size_t)(r2 + i) * H + h2;
            float4 p0 = *(const float4*)&Ob[(r2 + i) * 64 + h2];
            float4 p1 = *(const float4*)&Ob[(r2 + i) * 64 + h2 + 4];
            *(float4*)og       = make_float4(p0.x + oa[i][0], p0.y + oa[i][1], p0.z + oa[i][2], p0.w + oa[i][3]);
            *(float4*)(og + 4) = make_float4(p1.x + oa[i][4], p1.y + oa[i][5], p1.z + oa[i][6], p1.w + oa[i][7]);
        }
    }
}

extern "C" void kernel_launch(void* const* d_in, const int* in_sizes, int n_in,
                              void* d_out, int out_size)
{
    const float* q    = (const float*)d_in[0];
    const float* keys = (const float*)d_in[1];
    const float* vals = (const float*)d_in[2];
    const int*   mask = (const int*)d_in[3];
    float* out = (float*)d_out;

    cudaFuncSetAttribute(attn_kernel, cudaFuncAttributeMaxDynamicSharedMemorySize, SMEM_BYTES);
    attn_kernel<<<B * (T / TM), NTHR, SMEM_BYTES>>>(q, keys, vals, mask, out);
}

// round 4
// speedup vs baseline: 1.6273x; 1.6218x over previous
#include <cuda_runtime.h>
#include <cstdint>

static constexpr int B_ = 8, T_ = 2048, S_ = 2048, H_ = 64;
static constexpr int NT = 256;

// smem float offsets
static constexpr int KR    = 0;         // K raw: 128 rows x 72 (64 data + pad)
static constexpr int VR    = 9216;      // V^T raw: 64 rows x 136 (128 data + pad)
static constexpr int PR    = 17920;     // P raw: 128 rows x 136
static constexpr int LROW  = 35328;     // 128 inv-l
static constexpr int MBITS = 35456;     // 4 u32 mask bits
static constexpr int SMEMF = 35464;
static constexpr int SMEM_BYTES = SMEMF * 4;   // ~142 KB

__device__ __forceinline__ uint32_t f2tf(float x) {
    uint32_t r;
    asm("cvt.rna.tf32.f32 %0, %1;" : "=r"(r) : "f"(x));
    return r;
}

__device__ __forceinline__ void mma8(float* d, const uint32_t* a, uint32_t b0, uint32_t b1) {
    asm volatile(
        "mma.sync.aligned.m16n8k8.row.col.f32.tf32.tf32.f32 "
        "{%0,%1,%2,%3}, {%4,%5,%6,%7}, {%8,%9}, {%0,%1,%2,%3};"
        : "+f"(d[0]), "+f"(d[1]), "+f"(d[2]), "+f"(d[3])
        : "r"(a[0]), "r"(a[1]), "r"(a[2]), "r"(a[3]), "r"(b0), "r"(b1));
}

extern __shared__ float smf[];

__global__ void __launch_bounds__(NT, 1)
attn_mma(const float* __restrict__ q, const float* __restrict__ k,
         const float* __restrict__ v, const int* __restrict__ mask,
         float* __restrict__ out)
{
    const int tid = threadIdx.x;
    const int w = tid >> 5, lane = tid & 31;
    const int rw = lane >> 2, tm = lane & 3;
    const int bx = blockIdx.x;
    const int b = bx >> 4, t0 = (bx & 15) << 7;

    const float* qb = q + ((size_t)b * T_ + t0) * H_;
    const float* kb = k + (size_t)b * S_ * H_;
    const float* vb = v + (size_t)b * S_ * H_;
    const int*   mb = mask + (size_t)b * S_;
    float* pp = out + (size_t)B_ * T_ * H_ + ((size_t)b * T_ + t0) * S_;
    float* oo = out + ((size_t)b * T_ + t0) * H_;

    uint32_t* mbu = (uint32_t*)(smf + MBITS);
    const int prow = 16 * w + rw;

    // ---- Q fragments, pre-split hi/lo, held in registers for whole kernel ----
    uint32_t ah[8][4], al[8][4];
    #pragma unroll
    for (int ks = 0; ks < 8; ks++) {
        const int c = ks * 8 + tm;
        float x0 = qb[prow * 64 + c];
        float x1 = qb[(prow + 8) * 64 + c];
        float x2 = qb[prow * 64 + c + 4];
        float x3 = qb[(prow + 8) * 64 + c + 4];
        ah[ks][0] = f2tf(x0); al[ks][0] = __float_as_uint(x0 - __uint_as_float(ah[ks][0]));
        ah[ks][1] = f2tf(x1); al[ks][1] = __float_as_uint(x1 - __uint_as_float(ah[ks][1]));
        ah[ks][2] = f2tf(x2); al[ks][2] = __float_as_uint(x2 - __uint_as_float(ah[ks][2]));
        ah[ks][3] = f2tf(x3); al[ks][3] = __float_as_uint(x3 - __uint_as_float(ah[ks][3]));
    }

    float O[8][4];
    #pragma unroll
    for (int i = 0; i < 8; i++)
        #pragma unroll
        for (int jj = 0; jj < 4; jj++) O[i][jj] = 0.0f;
    float lac0 = 0.0f, lac1 = 0.0f;

    for (int j = 0; j < 16; j++) {
        const int s0 = j << 7;
        __syncthreads();   // previous tile's PV reads done

        // ---- stage K raw: Kt[s][perm(h)] stride 72 ----
        #pragma unroll
        for (int it = 0; it < 8; it++) {
            int i4 = (tid + it * 256) * 4;
            int s = i4 >> 6, h0 = i4 & 63;
            float4 val = *(const float4*)(kb + (size_t)s0 * H_ + i4);
            int base = KR + s * 72 + ((h0 >> 3) << 3) + ((h0 >> 2) & 1);
            smf[base]     = val.x;
            smf[base + 2] = val.y;
            smf[base + 4] = val.z;
            smf[base + 6] = val.w;
        }
        // ---- stage V transposed: Vt[h][perm(s)] stride 136 ----
        #pragma unroll
        for (int it = 0; it < 8; it++) {
            int i4 = (tid + it * 256) * 4;
            int s = i4 >> 6, h0 = i4 & 63;
            float4 val = *(const float4*)(vb + (size_t)s0 * H_ + i4);
            int kp = ((s >> 3) << 3) + (((s & 3) << 1) | ((s >> 2) & 1));
            int base = VR + h0 * 136 + kp;
            smf[base]       = val.x;
            smf[base + 136] = val.y;
            smf[base + 272] = val.z;
            smf[base + 408] = val.w;
        }
        if (tid < 128) {
            unsigned mv = __ballot_sync(0xffffffffu, mb[s0 + tid] != 0);
            if (lane == 0) mbu[w] = mv;
        }
        __syncthreads();

        // ---- QK^T (3xTF32) + exp epilogue ----
        #pragma unroll
        for (int nt = 0; nt < 16; nt++) {
            float d[4] = {0.f, 0.f, 0.f, 0.f};
            const int nrow = nt * 8 + rw;
            #pragma unroll
            for (int ks = 0; ks < 8; ks++) {
                float2 kr = *(const float2*)&smf[KR + nrow * 72 + ks * 8 + 2 * tm];
                uint32_t bh0 = f2tf(kr.x), bh1 = f2tf(kr.y);
                uint32_t bl0 = __float_as_uint(kr.x - __uint_as_float(bh0));
                uint32_t bl1 = __float_as_uint(kr.y - __uint_as_float(bh1));
                mma8(d, ah[ks], bh0, bh1);
                mma8(d, al[ks], bh0, bh1);
                mma8(d, ah[ks], bl0, bl1);
            }
            uint32_t wb = mbu[nt >> 2];
            int sh = ((nt & 3) << 3) + 2 * tm;
            float e0 = ((wb >> sh) & 1u)       ? __expf(d[0]) : 0.0f;
            float e1 = ((wb >> (sh + 1)) & 1u) ? __expf(d[1]) : 0.0f;
            float e2 = ((wb >> sh) & 1u)       ? __expf(d[2]) : 0.0f;
            float e3 = ((wb >> (sh + 1)) & 1u) ? __expf(d[3]) : 0.0f;
            lac0 += e0 + e1;
            lac1 += e2 + e3;
            const int cg = nt * 8 + 2 * tm;
            __stcs((float2*)(pp + (size_t)prow * S_ + s0 + cg), make_float2(e0, e1));
            __stcs((float2*)(pp + (size_t)(prow + 8) * S_ + s0 + cg), make_float2(e2, e3));
            // stash raw p in smem (perm layout for A-frag reload)
            int i0 = ((2 * tm) & 3) * 2 + ((2 * tm) >> 2);   // {0,4,1,5}
            int pbase = PR + prow * 136 + nt * 8;
            smf[pbase + i0]               = e0;
            smf[pbase + i0 + 2]           = e1;
            smf[pbase + 8 * 136 + i0]     = e2;
            smf[pbase + 8 * 136 + i0 + 2] = e3;
        }
        __syncwarp();

        // ---- PV (3xTF32), O += P_unnorm @ V ----
        #pragma unroll
        for (int kb4 = 0; kb4 < 4; kb4++) {
            uint32_t pah[4][4], pal[4][4];
            #pragma unroll
            for (int kq = 0; kq < 4; kq++) {
                int ks = kb4 * 4 + kq;
                float2 p0 = *(const float2*)&smf[PR + prow * 136 + ks * 8 + 2 * tm];
                float2 p1 = *(const float2*)&smf[PR + (prow + 8) * 136 + ks * 8 + 2 * tm];
                pah[kq][0] = f2tf(p0.x); pal[kq][0] = __float_as_uint(p0.x - __uint_as_float(pah[kq][0]));
                pah[kq][1] = f2tf(p1.x); pal[kq][1] = __float_as_uint(p1.x - __uint_as_float(pah[kq][1]));
                pah[kq][2] = f2tf(p0.y); pal[kq][2] = __float_as_uint(p0.y - __uint_as_float(pah[kq][2]));
                pah[kq][3] = f2tf(p1.y); pal[kq][3] = __float_as_uint(p1.y - __uint_as_float(pah[kq][3]));
            }
            #pragma unroll
            for (int nt = 0; nt < 8; nt++) {
                const int vrow = nt * 8 + rw;
                #pragma unroll
                for (int kq = 0; kq < 4; kq++) {
                    int ks = kb4 * 4 + kq;
                    float2 vr2 = *(const float2*)&smf[VR + vrow * 136 + ks * 8 + 2 * tm];
                    uint32_t bh0 = f2tf(vr2.x), bh1 = f2tf(vr2.y);
                    uint32_t bl0 = __float_as_uint(vr2.x - __uint_as_float(bh0));
                    uint32_t bl1 = __float_as_uint(vr2.y - __uint_as_float(bh1));
                    mma8(O[nt], pah[kq], bh0, bh1);
                    mma8(O[nt], pal[kq], bh0, bh1);
                    mma8(O[nt], pah[kq], bl0, bl1);
                }
            }
        }
    }

    // ---- reduce l across the 4 lanes sharing each row, store 1/l ----
    lac0 += __shfl_xor_sync(0xffffffffu, lac0, 1);
    lac0 += __shfl_xor_sync(0xffffffffu, lac0, 2);
    lac1 += __shfl_xor_sync(0xffffffffu, lac1, 1);
    lac1 += __shfl_xor_sync(0xffffffffu, lac1, 2);
    if (tm == 0) {
        smf[LROW + prow]     = 1.0f / lac0;
        smf[LROW + prow + 8] = 1.0f / lac1;
    }
    __syncthreads();
    const float il0 = smf[LROW + prow];
    const float il1 = smf[LROW + prow + 8];

    // ---- write O ----
    #pragma unroll
    for (int nt = 0; nt < 8; nt++) {
        int c = nt * 8 + 2 * tm;
        *(float2*)(oo + (size_t)prow * H_ + c)       = make_float2(O[nt][0] * il0, O[nt][1] * il0);
        *(float2*)(oo + (size_t)(prow + 8) * H_ + c) = make_float2(O[nt][2] * il1, O[nt][3] * il1);
    }

    // ---- rescale p (coalesced sweep over this CTA's 128x2048 slice) ----
    for (int i = tid; i < 128 * 512; i += NT) {
        int row = i >> 9, c4 = i & 511;
        float il = smf[LROW + row];
        float4* g = (float4*)(pp + (size_t)row * S_) + c4;
        float4 vv = __ldcs(g);
        vv.x *= il; vv.y *= il; vv.z *= il; vv.w *= il;
        __stcs(g, vv);
    }
}

extern "C" void kernel_launch(void* const* d_in, const int* in_sizes, int n_in,
                              void* d_out, int out_size)
{
    const float* q    = (const float*)d_in[0];
    const float* keys = (const float*)d_in[1];
    const float* vals = (const float*)d_in[2];
    const int*   mask = (const int*)d_in[3];
    float* out = (float*)d_out;

    cudaFuncSetAttribute(attn_mma, cudaFuncAttributeMaxDynamicSharedMemorySize, SMEM_BYTES);
    attn_mma<<<B_ * (T_ / 128), NT, SMEM_BYTES>>>(q, keys, vals, mask, out);
}